// round 12
// baseline (speedup 1.0000x reference)
#include <cuda_runtime.h>
#include <math.h>

// BoundaryLoss: exact squared-EDT via separable min-convolution. 2 kernels:
// k_wh:     per (vol, d-slice, w-chunk): ballot targets -> W nearest-zero
//           distance -> windowed H min-conv (unroll x4) -> packed u32 store.
// k_fuse_d: windowed D min-conv + 2-exp softmax + signed-dist + deterministic
//           fixed-point reduction. float2 smem tiles, per-warp windows.
// Shapes: B=2, C=3, D=H=W=96.

#define N2 9216           // 96*96
#define N3 884736         // 96^3
#define SENTI 65535
#define THRSF 32768.0f    // real <= 27075 < 32768 <= sentinel-derived

__device__ unsigned g_pack[4 * N3];    // 14.2 MB packed scratch (pos|neg<<16)
__device__ unsigned g_cntpart[384];    // per (vol, d-slice) mask counts
__device__ unsigned long long g_sum;   // fixed-point (x 2^24) loss numerator
__device__ unsigned g_tick = 0;        // monotonic ticket (mod 1152 per launch)

// ---------------------------------------------- nearest zero bit in 96 bits
__device__ __forceinline__ int near_zero_dist(unsigned z0, unsigned z1, unsigned z2,
                                              int w, int r) {
    unsigned lowm = (2u << r) - 1u;
    unsigned him  = 0xffffffffu << r;
    int dl = 1000, dr = 1000;
    if (w == 0) {
        unsigned u = z0 & lowm;
        if (u) dl = r - (31 - __clz(u));
        unsigned v = z0 & him;
        if (v)       dr = (__ffs(v) - 1) - r;
        else if (z1) dr = 32 - r + (__ffs(z1) - 1);
        else if (z2) dr = 64 - r + (__ffs(z2) - 1);
    } else if (w == 1) {
        unsigned u = z1 & lowm;
        if (u)       dl = r - (31 - __clz(u));
        else if (z0) dl = r + 1 + __clz(z0);
        unsigned v = z1 & him;
        if (v)       dr = (__ffs(v) - 1) - r;
        else if (z2) dr = 32 - r + (__ffs(z2) - 1);
    } else {
        unsigned u = z2 & lowm;
        if (u)       dl = r - (31 - __clz(u));
        else if (z1) dl = r + 1 + __clz(z1);
        else if (z0) dl = r + 33 + __clz(z0);
        unsigned v = z2 & him;
        if (v) dr = (__ffs(v) - 1) - r;
    }
    return min(dl, dr);
}

// --------------------------------------------------- fused W + H pass
// Grid: 1152 = vb(2b x 2cls)*288 + d-slice*3 + w-chunk ; 512 threads.
__global__ void __launch_bounds__(512, 3) k_wh(const void* __restrict__ tptr) {
    __shared__ float2 sh[32 * 97];     // [w-row][h], pitch 97
    __shared__ int scnt;
    int bid = blockIdx.x;
    int vb = bid / 288, rem = bid % 288;
    int s = rem / 3, wc = rem % 3;
    int b = vb >> 1, clsv = (vb & 1) + 1;
    int lane = threadIdx.x & 31, wid = threadIdx.x >> 5;   // 16 warps

    const int* t32 = (const int*)tptr;
    if (threadIdx.x == 0) scnt = 0;
    // dtype probe: int64 targets in [0,2] -> all odd int32 words zero
    int any = (threadIdx.x < 64) ? (t32[2 * threadIdx.x + 1] != 0) : 0;
    int is64 = !__syncthreads_or(any);   // also orders scnt init

    int tb = b * N3 + s * N2;
    int cnt = 0;
    #pragma unroll
    for (int k = 0; k < 6; k++) {
        int h = wid + 16 * k;
        int t0, t1, t2;
        if (!is64) {
            const int* T = t32 + tb + h * 96;
            t0 = T[lane]; t1 = T[lane + 32]; t2 = T[lane + 64];
        } else {
            const long long* T = (const long long*)tptr + tb + h * 96;
            t0 = (int)T[lane]; t1 = (int)T[lane + 32]; t2 = (int)T[lane + 64];
        }
        unsigned m0 = __ballot_sync(0xffffffffu, t0 == clsv);
        unsigned m1 = __ballot_sync(0xffffffffu, t1 == clsv);
        unsigned m2 = __ballot_sync(0xffffffffu, t2 == clsv);
        if (wc == 0) cnt += __popc(m0) + __popc(m1) + __popc(m2);
        int dp = near_zero_dist(~m0, ~m1, ~m2, wc, lane);
        int dn = near_zero_dist(m0, m1, m2, wc, lane);
        int h2 = h * h;
        sh[lane * 97 + h] = make_float2(
            (float)(((dp > 95) ? SENTI : dp * dp) + h2),
            (float)(((dn > 95) ? SENTI : dn * dn) + h2));
    }
    if (wc == 0 && lane == 0) atomicAdd(&scnt, cnt);
    __syncthreads();
    if (wc == 0 && threadIdx.x == 0) g_cntpart[vb * 96 + s] = (unsigned)scnt;
    if (bid == 0 && threadIdx.x == 0) g_sum = 0ULL;

    // phase 2: min-conv along h for this thread's 6 outputs at w-row tx
    int tx = lane, ty = wid;
    int i0 = ty * 6;
    const float2* sp = sh + tx * 97;

    float fi[6];
    #pragma unroll
    for (int k = 0; k < 6; k++) fi[k] = (float)(i0 + k);

    // per-warp exact window: R >= sqrt(f[i]) for every output in the warp
    float fm = 0.f;
    #pragma unroll
    for (int k = 0; k < 6; k++) {
        float2 u = sp[i0 + k];
        fm = fmaxf(fm, fmaxf(u.x, u.y) - fi[k] * fi[k]);
    }
    #pragma unroll
    for (int off = 16; off; off >>= 1)
        fm = fmaxf(fm, __shfl_xor_sync(0xffffffffu, fm, off));
    int R = (fm >= THRSF) ? 95 : min(95, (int)floorf(sqrtf(fm)) + 1);

    int j0 = max(0, i0 - R), j1 = min(95, i0 + 5 + R);
    float v0[6], v1[6];
    #pragma unroll
    for (int k = 0; k < 6; k++) { v0[k] = 3.0e38f; v1[k] = 3.0e38f; }

    float m2a = -2.0f * (float)j0;
    int j = j0;
    for (; j + 3 <= j1; j += 4) {                 // unroll x4
        float2 a = sp[j], bb = sp[j + 1], c = sp[j + 2], d = sp[j + 3];
        float m2b = m2a - 2.0f, m2c = m2a - 4.0f, m2d = m2a - 6.0f;
        #pragma unroll
        for (int k = 0; k < 6; k++) {
            v0[k] = fminf(v0[k], fmaf(m2a, fi[k], a.x));
            v1[k] = fminf(v1[k], fmaf(m2a, fi[k], a.y));
            v0[k] = fminf(v0[k], fmaf(m2b, fi[k], bb.x));
            v1[k] = fminf(v1[k], fmaf(m2b, fi[k], bb.y));
            v0[k] = fminf(v0[k], fmaf(m2c, fi[k], c.x));
            v1[k] = fminf(v1[k], fmaf(m2c, fi[k], c.y));
            v0[k] = fminf(v0[k], fmaf(m2d, fi[k], d.x));
            v1[k] = fminf(v1[k], fmaf(m2d, fi[k], d.y));
        }
        m2a -= 8.0f;
    }
    for (; j <= j1; j++) {
        float2 a = sp[j];
        #pragma unroll
        for (int k = 0; k < 6; k++) {
            v0[k] = fminf(v0[k], fmaf(m2a, fi[k], a.x));
            v1[k] = fminf(v1[k], fmaf(m2a, fi[k], a.y));
        }
        m2a -= 2.0f;
    }

    unsigned* outp = g_pack + (size_t)vb * N3 + (size_t)s * N2 + wc * 32 + tx;
    #pragma unroll
    for (int k = 0; k < 6; k++) {
        float i2 = fi[k] * fi[k];
        float r0 = v0[k] + i2;
        float r1 = v1[k] + i2;
        unsigned e0 = (r0 >= THRSF) ? (unsigned)SENTI : (unsigned)__float2int_rn(r0);
        unsigned e1 = (r1 >= THRSF) ? (unsigned)SENTI : (unsigned)__float2int_rn(r1);
        outp[(size_t)(i0 + k) * 96] = e0 | (e1 << 16);
    }
}

// ------------------------------------------- fused D pass + softmax reduce
// Grid: 4 packed vols (b,cls) * 96 h-slices * 3 w-chunks = 1152 blocks x 512.
__global__ void __launch_bounds__(512, 4) k_fuse_d(const float* __restrict__ logits,
                                                   float* __restrict__ outp) {
    __shared__ float2 sh[96 * 32];     // 24.6 KB: [d-row][w]
    __shared__ float swred[16];
    int bid = blockIdx.x;
    int vb = bid / 288, rem = bid % 288;
    int s = rem / 3, wc = rem % 3;
    int b = vb >> 1, cls = vb & 1;
    int tx = threadIdx.x & 31, ty = threadIdx.x >> 5;
    unsigned nbase = (unsigned)s * 96 + wc * 32 + tx;   // voxel idx: + d*N2

    // gate = mask.any() for this (b, cls): OR over its 96 per-slice counts
    int pred = (threadIdx.x < 96) ? (g_cntpart[vb * 96 + threadIdx.x] != 0) : 0;
    float gate = __syncthreads_or(pred) ? 1.f : 0.f;

    const unsigned* p = g_pack + (size_t)vb * N3 + nbase;
    #pragma unroll
    for (int r = ty; r < 96; r += 16) {
        unsigned u = p[(size_t)r * N2];
        float r2 = (float)(r * r);
        sh[r * 32 + tx] = make_float2((float)(u & 0xffffu) + r2,
                                      (float)(u >> 16) + r2);
    }
    __syncthreads();

    int i0 = ty * 6;
    float fi[6];
    #pragma unroll
    for (int k = 0; k < 6; k++) fi[k] = (float)(i0 + k);

    const float2* sp = sh + tx;

    // per-warp exact window radius
    float fm = 0.f;
    #pragma unroll
    for (int k = 0; k < 6; k++) {
        float2 u = sp[(i0 + k) * 32];
        fm = fmaxf(fm, fmaxf(u.x, u.y) - fi[k] * fi[k]);
    }
    #pragma unroll
    for (int off = 16; off; off >>= 1)
        fm = fmaxf(fm, __shfl_xor_sync(0xffffffffu, fm, off));
    int R = (fm >= THRSF) ? 95 : min(95, (int)floorf(sqrtf(fm)) + 1);

    int j0 = max(0, i0 - R), j1 = min(95, i0 + 5 + R);
    float v0[6], v1[6];
    #pragma unroll
    for (int k = 0; k < 6; k++) { v0[k] = 3.0e38f; v1[k] = 3.0e38f; }

    float m2a = -2.0f * (float)j0;
    int j = j0;
    for (; j + 1 <= j1; j += 2) {
        float2 a = sp[j * 32], bb = sp[j * 32 + 32];
        float m2b = m2a - 2.0f;
        #pragma unroll
        for (int k = 0; k < 6; k++) {
            v0[k] = fminf(v0[k], fmaf(m2a, fi[k], a.x));
            v1[k] = fminf(v1[k], fmaf(m2a, fi[k], a.y));
            v0[k] = fminf(v0[k], fmaf(m2b, fi[k], bb.x));
            v1[k] = fminf(v1[k], fmaf(m2b, fi[k], bb.y));
        }
        m2a -= 4.0f;
    }
    if (j == j1) {
        float2 a = sp[j * 32];
        #pragma unroll
        for (int k = 0; k < 6; k++) {
            v0[k] = fminf(v0[k], fmaf(m2a, fi[k], a.x));
            v1[k] = fminf(v1[k], fmaf(m2a, fi[k], a.y));
        }
    }

    // epilogue: sd = sqrt(neg) - sqrt(pos); 2-exp softmax of this class; gate
    const float* L = logits + (size_t)b * 3 * N3 + nbase + (size_t)i0 * N2;
    float acc = 0.f;
    #pragma unroll
    for (int k = 0; k < 6; k++) {
        float i2 = fi[k] * fi[k];
        float r0 = v0[k] + i2;
        float r1 = v1[k] + i2;
        float f0 = (r0 >= THRSF) ? 1e8f : r0;
        float f1 = (r1 >= THRSF) ? 1e8f : r1;
        float sd = sqrtf(f1) - sqrtf(f0);
        float l0 = L[0], l1 = L[(size_t)N3], l2 = L[(size_t)2 * N3];
        L += N2;
        // p_c = 1 / (e^{l0-lc} + e^{lo-lc} + 1), own term == 1
        float lc = cls ? l2 : l1;
        float lo = cls ? l1 : l2;
        float sum = __expf(l0 - lc) + __expf(lo - lc) + 1.0f;
        acc += __fdividef(sd, sum);
    }
    acc *= gate;

    #pragma unroll
    for (int off = 16; off; off >>= 1)
        acc += __shfl_down_sync(0xffffffffu, acc, off);
    if (tx == 0) swred[ty] = acc;
    __syncthreads();
    if (threadIdx.x == 0) {
        float t = 0.f;
        #pragma unroll
        for (int i = 0; i < 16; i++) t += swred[i];
        // exact power-of-two scale -> deterministic integer accumulation
        long long q = llrintf(t * 16777216.0f);
        atomicAdd(&g_sum, (unsigned long long)q);
        __threadfence();
        unsigned tk = atomicAdd(&g_tick, 1u);
        if ((tk % 1152u) == 1151u) {
            long long ssum = (long long)atomicAdd(&g_sum, 0ULL);
            outp[0] = (float)((double)ssum / 16777216.0 / (2.0 * (double)N3));
        }
    }
}

// ---------------------------------------------------------------- launch
extern "C" void kernel_launch(void* const* d_in, const int* in_sizes, int n_in,
                              void* d_out, int out_size) {
    const float* logits = (const float*)d_in[0];
    const void*  targets = d_in[1];
    float* out = (float*)d_out;
    (void)in_sizes; (void)n_in; (void)out_size;

    k_wh<<<1152, 512>>>(targets);
    k_fuse_d<<<1152, 512>>>(logits, out);
}

// round 13
// speedup vs baseline: 1.0918x; 1.0918x over previous
#include <cuda_runtime.h>
#include <math.h>

// BoundaryLoss: exact squared-EDT via separable min-convolution. 2 kernels:
// k_wh:     per (vol, d-slice, w-chunk): ballot targets -> W nearest-zero
//           distance -> windowed H min-conv (unroll x2) -> packed u32 store.
// k_fuse_d: windowed D min-conv + 2-exp softmax + rsqrt-based signed-dist +
//           deterministic fixed-point reduction. float2 smem tiles.
// Shapes: B=2, C=3, D=H=W=96.

#define N2 9216           // 96*96
#define N3 884736         // 96^3
#define SENTI 65535
#define THRSF 32768.0f    // real <= 27075 < 32768 <= sentinel-derived

__device__ unsigned g_pack[4 * N3];    // 14.2 MB packed scratch (pos|neg<<16)
__device__ unsigned g_cntpart[384];    // per (vol, d-slice) mask counts
__device__ unsigned long long g_sum;   // fixed-point (x 2^24) loss numerator
__device__ unsigned g_tick = 0;        // monotonic ticket (mod 1152 per launch)

// fast exact-enough sqrt: one MUFU.RSQ + one FMUL; x=0 -> 0 (not NaN)
__device__ __forceinline__ float fsqrt_pos(float x) {
    return x * rsqrtf(x + 1e-20f);
}

// ---------------------------------------------- nearest zero bit in 96 bits
__device__ __forceinline__ int near_zero_dist(unsigned z0, unsigned z1, unsigned z2,
                                              int w, int r) {
    unsigned lowm = (2u << r) - 1u;
    unsigned him  = 0xffffffffu << r;
    int dl = 1000, dr = 1000;
    if (w == 0) {
        unsigned u = z0 & lowm;
        if (u) dl = r - (31 - __clz(u));
        unsigned v = z0 & him;
        if (v)       dr = (__ffs(v) - 1) - r;
        else if (z1) dr = 32 - r + (__ffs(z1) - 1);
        else if (z2) dr = 64 - r + (__ffs(z2) - 1);
    } else if (w == 1) {
        unsigned u = z1 & lowm;
        if (u)       dl = r - (31 - __clz(u));
        else if (z0) dl = r + 1 + __clz(z0);
        unsigned v = z1 & him;
        if (v)       dr = (__ffs(v) - 1) - r;
        else if (z2) dr = 32 - r + (__ffs(z2) - 1);
    } else {
        unsigned u = z2 & lowm;
        if (u)       dl = r - (31 - __clz(u));
        else if (z1) dl = r + 1 + __clz(z1);
        else if (z0) dl = r + 33 + __clz(z0);
        unsigned v = z2 & him;
        if (v) dr = (__ffs(v) - 1) - r;
    }
    return min(dl, dr);
}

// --------------------------------------------------- fused W + H pass
// Grid: 1152 = vb(2b x 2cls)*288 + d-slice*3 + w-chunk ; 512 threads.
__global__ void __launch_bounds__(512, 3) k_wh(const void* __restrict__ tptr) {
    __shared__ float2 sh[32 * 97];     // [w-row][h], pitch 97
    __shared__ int scnt;
    int bid = blockIdx.x;
    int vb = bid / 288, rem = bid % 288;
    int s = rem / 3, wc = rem % 3;
    int b = vb >> 1, clsv = (vb & 1) + 1;
    int lane = threadIdx.x & 31, wid = threadIdx.x >> 5;   // 16 warps

    const int* t32 = (const int*)tptr;
    if (threadIdx.x == 0) scnt = 0;
    // dtype probe: int64 targets in [0,2] -> all odd int32 words zero
    int any = (threadIdx.x < 64) ? (t32[2 * threadIdx.x + 1] != 0) : 0;
    int is64 = !__syncthreads_or(any);   // also orders scnt init

    int tb = b * N3 + s * N2;
    int cnt = 0;
    #pragma unroll
    for (int k = 0; k < 6; k++) {
        int h = wid + 16 * k;
        int t0, t1, t2;
        if (!is64) {
            const int* T = t32 + tb + h * 96;
            t0 = T[lane]; t1 = T[lane + 32]; t2 = T[lane + 64];
        } else {
            const long long* T = (const long long*)tptr + tb + h * 96;
            t0 = (int)T[lane]; t1 = (int)T[lane + 32]; t2 = (int)T[lane + 64];
        }
        unsigned m0 = __ballot_sync(0xffffffffu, t0 == clsv);
        unsigned m1 = __ballot_sync(0xffffffffu, t1 == clsv);
        unsigned m2 = __ballot_sync(0xffffffffu, t2 == clsv);
        if (wc == 0) cnt += __popc(m0) + __popc(m1) + __popc(m2);
        int dp = near_zero_dist(~m0, ~m1, ~m2, wc, lane);
        int dn = near_zero_dist(m0, m1, m2, wc, lane);
        int h2 = h * h;
        sh[lane * 97 + h] = make_float2(
            (float)(((dp > 95) ? SENTI : dp * dp) + h2),
            (float)(((dn > 95) ? SENTI : dn * dn) + h2));
    }
    if (wc == 0 && lane == 0) atomicAdd(&scnt, cnt);
    __syncthreads();
    if (wc == 0 && threadIdx.x == 0) g_cntpart[vb * 96 + s] = (unsigned)scnt;
    if (bid == 0 && threadIdx.x == 0) g_sum = 0ULL;

    // phase 2: min-conv along h for this thread's 6 outputs at w-row tx
    int tx = lane, ty = wid;
    int i0 = ty * 6;
    const float2* sp = sh + tx * 97;

    float fi[6];
    #pragma unroll
    for (int k = 0; k < 6; k++) fi[k] = (float)(i0 + k);

    // per-warp exact window: R >= sqrt(f[i]) for every output in the warp
    float fm = 0.f;
    #pragma unroll
    for (int k = 0; k < 6; k++) {
        float2 u = sp[i0 + k];
        fm = fmaxf(fm, fmaxf(u.x, u.y) - fi[k] * fi[k]);
    }
    #pragma unroll
    for (int off = 16; off; off >>= 1)
        fm = fmaxf(fm, __shfl_xor_sync(0xffffffffu, fm, off));
    int R = (fm >= THRSF) ? 95 : min(95, (int)floorf(fsqrt_pos(fm)) + 1);

    int j0 = max(0, i0 - R), j1 = min(95, i0 + 5 + R);
    float v0[6], v1[6];
    #pragma unroll
    for (int k = 0; k < 6; k++) { v0[k] = 3.0e38f; v1[k] = 3.0e38f; }

    float m2a = -2.0f * (float)j0;
    int j = j0;
    for (; j + 1 <= j1; j += 2) {
        float2 a = sp[j], bb = sp[j + 1];
        float m2b = m2a - 2.0f;
        #pragma unroll
        for (int k = 0; k < 6; k++) {
            v0[k] = fminf(v0[k], fmaf(m2a, fi[k], a.x));
            v1[k] = fminf(v1[k], fmaf(m2a, fi[k], a.y));
            v0[k] = fminf(v0[k], fmaf(m2b, fi[k], bb.x));
            v1[k] = fminf(v1[k], fmaf(m2b, fi[k], bb.y));
        }
        m2a -= 4.0f;
    }
    if (j == j1) {
        float2 a = sp[j];
        #pragma unroll
        for (int k = 0; k < 6; k++) {
            v0[k] = fminf(v0[k], fmaf(m2a, fi[k], a.x));
            v1[k] = fminf(v1[k], fmaf(m2a, fi[k], a.y));
        }
    }

    unsigned* outp = g_pack + (size_t)vb * N3 + (size_t)s * N2 + wc * 32 + tx;
    #pragma unroll
    for (int k = 0; k < 6; k++) {
        float i2 = fi[k] * fi[k];
        float r0 = v0[k] + i2;
        float r1 = v1[k] + i2;
        unsigned e0 = (r0 >= THRSF) ? (unsigned)SENTI : (unsigned)__float2int_rn(r0);
        unsigned e1 = (r1 >= THRSF) ? (unsigned)SENTI : (unsigned)__float2int_rn(r1);
        outp[(size_t)(i0 + k) * 96] = e0 | (e1 << 16);
    }
}

// ------------------------------------------- fused D pass + softmax reduce
// Grid: 4 packed vols (b,cls) * 96 h-slices * 3 w-chunks = 1152 blocks x 512.
__global__ void __launch_bounds__(512, 4) k_fuse_d(const float* __restrict__ logits,
                                                   float* __restrict__ outp) {
    __shared__ float2 sh[96 * 32];     // 24.6 KB: [d-row][w]
    __shared__ float swred[16];
    int bid = blockIdx.x;
    int vb = bid / 288, rem = bid % 288;
    int s = rem / 3, wc = rem % 3;
    int b = vb >> 1, cls = vb & 1;
    int tx = threadIdx.x & 31, ty = threadIdx.x >> 5;
    unsigned nbase = (unsigned)s * 96 + wc * 32 + tx;   // voxel idx: + d*N2

    // gate = mask.any() for this (b, cls): OR over its 96 per-slice counts
    int pred = (threadIdx.x < 96) ? (g_cntpart[vb * 96 + threadIdx.x] != 0) : 0;
    float gate = __syncthreads_or(pred) ? 1.f : 0.f;

    const unsigned* p = g_pack + (size_t)vb * N3 + nbase;
    #pragma unroll
    for (int r = ty; r < 96; r += 16) {
        unsigned u = p[(size_t)r * N2];
        float r2 = (float)(r * r);
        sh[r * 32 + tx] = make_float2((float)(u & 0xffffu) + r2,
                                      (float)(u >> 16) + r2);
    }
    __syncthreads();

    int i0 = ty * 6;
    float fi[6];
    #pragma unroll
    for (int k = 0; k < 6; k++) fi[k] = (float)(i0 + k);

    const float2* sp = sh + tx;

    // per-warp exact window radius
    float fm = 0.f;
    #pragma unroll
    for (int k = 0; k < 6; k++) {
        float2 u = sp[(i0 + k) * 32];
        fm = fmaxf(fm, fmaxf(u.x, u.y) - fi[k] * fi[k]);
    }
    #pragma unroll
    for (int off = 16; off; off >>= 1)
        fm = fmaxf(fm, __shfl_xor_sync(0xffffffffu, fm, off));
    int R = (fm >= THRSF) ? 95 : min(95, (int)floorf(fsqrt_pos(fm)) + 1);

    int j0 = max(0, i0 - R), j1 = min(95, i0 + 5 + R);
    float v0[6], v1[6];
    #pragma unroll
    for (int k = 0; k < 6; k++) { v0[k] = 3.0e38f; v1[k] = 3.0e38f; }

    float m2a = -2.0f * (float)j0;
    int j = j0;
    for (; j + 1 <= j1; j += 2) {
        float2 a = sp[j * 32], bb = sp[j * 32 + 32];
        float m2b = m2a - 2.0f;
        #pragma unroll
        for (int k = 0; k < 6; k++) {
            v0[k] = fminf(v0[k], fmaf(m2a, fi[k], a.x));
            v1[k] = fminf(v1[k], fmaf(m2a, fi[k], a.y));
            v0[k] = fminf(v0[k], fmaf(m2b, fi[k], bb.x));
            v1[k] = fminf(v1[k], fmaf(m2b, fi[k], bb.y));
        }
        m2a -= 4.0f;
    }
    if (j == j1) {
        float2 a = sp[j * 32];
        #pragma unroll
        for (int k = 0; k < 6; k++) {
            v0[k] = fminf(v0[k], fmaf(m2a, fi[k], a.x));
            v1[k] = fminf(v1[k], fmaf(m2a, fi[k], a.y));
        }
    }

    // epilogue: sd = sqrt(neg) - sqrt(pos); 2-exp softmax of this class; gate
    const float* L = logits + (size_t)b * 3 * N3 + nbase + (size_t)i0 * N2;
    float acc = 0.f;
    #pragma unroll
    for (int k = 0; k < 6; k++) {
        float i2 = fi[k] * fi[k];
        float r0 = v0[k] + i2;
        float r1 = v1[k] + i2;
        float f0 = (r0 >= THRSF) ? 1e8f : r0;
        float f1 = (r1 >= THRSF) ? 1e8f : r1;
        float sd = fsqrt_pos(f1) - fsqrt_pos(f0);
        float l0 = L[0], l1 = L[(size_t)N3], l2 = L[(size_t)2 * N3];
        L += N2;
        // p_c = 1 / (e^{l0-lc} + e^{lo-lc} + 1), own term == 1
        float lc = cls ? l2 : l1;
        float lo = cls ? l1 : l2;
        float sum = __expf(l0 - lc) + __expf(lo - lc) + 1.0f;
        acc += __fdividef(sd, sum);
    }
    acc *= gate;

    #pragma unroll
    for (int off = 16; off; off >>= 1)
        acc += __shfl_down_sync(0xffffffffu, acc, off);
    if (tx == 0) swred[ty] = acc;
    __syncthreads();
    if (threadIdx.x == 0) {
        float t = 0.f;
        #pragma unroll
        for (int i = 0; i < 16; i++) t += swred[i];
        // exact power-of-two scale -> deterministic integer accumulation
        long long q = llrintf(t * 16777216.0f);
        atomicAdd(&g_sum, (unsigned long long)q);
        __threadfence();
        unsigned tk = atomicAdd(&g_tick, 1u);
        if ((tk % 1152u) == 1151u) {
            long long ssum = (long long)atomicAdd(&g_sum, 0ULL);
            outp[0] = (float)((double)ssum / 16777216.0 / (2.0 * (double)N3));
        }
    }
}

// ---------------------------------------------------------------- launch
extern "C" void kernel_launch(void* const* d_in, const int* in_sizes, int n_in,
                              void* d_out, int out_size) {
    const float* logits = (const float*)d_in[0];
    const void*  targets = d_in[1];
    float* out = (float*)d_out;
    (void)in_sizes; (void)n_in; (void)out_size;

    k_wh<<<1152, 512>>>(targets);
    k_fuse_d<<<1152, 512>>>(logits, out);
}

// round 14
// speedup vs baseline: 1.0925x; 1.0006x over previous
#include <cuda_runtime.h>
#include <math.h>

// BoundaryLoss: exact squared-EDT via separable min-convolution. 2 kernels:
// k_wh:     per (vol, d-slice, w-chunk): ballot targets -> ONE nearest-
//           opposite-bit search per voxel (polarity identity) -> windowed H
//           min-conv (unroll x2) -> packed u32 store.
// k_fuse_d: windowed D min-conv + 2-exp softmax + rsqrt signed-dist +
//           deterministic fixed-point reduction. float2 smem tiles.
// Shapes: B=2, C=3, D=H=W=96.

#define N2 9216           // 96*96
#define N3 884736         // 96^3
#define SENTI 65535
#define THRSF 32768.0f    // real <= 27075 < 32768 <= sentinel-derived

__device__ unsigned g_pack[4 * N3];    // 14.2 MB packed scratch (pos|neg<<16)
__device__ unsigned g_cntpart[384];    // per (vol, d-slice) mask counts
__device__ unsigned long long g_sum;   // fixed-point (x 2^24) loss numerator
__device__ unsigned g_tick = 0;        // monotonic ticket (mod 1152 per launch)

// fast exact-enough sqrt: one MUFU.RSQ + one FMUL; x=0 -> 0 (not NaN)
__device__ __forceinline__ float fsqrt_pos(float x) {
    return x * rsqrtf(x + 1e-20f);
}

// ------------------------------------- nearest SET bit in 96-bit mask
__device__ __forceinline__ int near_zero_dist(unsigned z0, unsigned z1, unsigned z2,
                                              int w, int r) {
    unsigned lowm = (2u << r) - 1u;
    unsigned him  = 0xffffffffu << r;
    int dl = 1000, dr = 1000;
    if (w == 0) {
        unsigned u = z0 & lowm;
        if (u) dl = r - (31 - __clz(u));
        unsigned v = z0 & him;
        if (v)       dr = (__ffs(v) - 1) - r;
        else if (z1) dr = 32 - r + (__ffs(z1) - 1);
        else if (z2) dr = 64 - r + (__ffs(z2) - 1);
    } else if (w == 1) {
        unsigned u = z1 & lowm;
        if (u)       dl = r - (31 - __clz(u));
        else if (z0) dl = r + 1 + __clz(z0);
        unsigned v = z1 & him;
        if (v)       dr = (__ffs(v) - 1) - r;
        else if (z2) dr = 32 - r + (__ffs(z2) - 1);
    } else {
        unsigned u = z2 & lowm;
        if (u)       dl = r - (31 - __clz(u));
        else if (z1) dl = r + 1 + __clz(z1);
        else if (z0) dl = r + 33 + __clz(z0);
        unsigned v = z2 & him;
        if (v) dr = (__ffs(v) - 1) - r;
    }
    return min(dl, dr);
}

// --------------------------------------------------- fused W + H pass
// Grid: 1152 = vb(2b x 2cls)*288 + d-slice*3 + w-chunk ; 512 threads.
__global__ void __launch_bounds__(512, 3) k_wh(const void* __restrict__ tptr) {
    __shared__ float2 sh[32 * 97];     // [w-row][h], pitch 97
    __shared__ int scnt;
    int bid = blockIdx.x;
    int vb = bid / 288, rem = bid % 288;
    int s = rem / 3, wc = rem % 3;
    int b = vb >> 1, clsv = (vb & 1) + 1;
    int lane = threadIdx.x & 31, wid = threadIdx.x >> 5;   // 16 warps

    const int* t32 = (const int*)tptr;
    if (threadIdx.x == 0) scnt = 0;
    // dtype probe: int64 targets in [0,2] -> all odd int32 words zero
    int any = (threadIdx.x < 64) ? (t32[2 * threadIdx.x + 1] != 0) : 0;
    int is64 = !__syncthreads_or(any);   // also orders scnt init

    int tb = b * N3 + s * N2;
    int cnt = 0;
    #pragma unroll
    for (int k = 0; k < 6; k++) {
        int h = wid + 16 * k;
        int t0, t1, t2;
        if (!is64) {
            const int* T = t32 + tb + h * 96;
            t0 = T[lane]; t1 = T[lane + 32]; t2 = T[lane + 64];
        } else {
            const long long* T = (const long long*)tptr + tb + h * 96;
            t0 = (int)T[lane]; t1 = (int)T[lane + 32]; t2 = (int)T[lane + 64];
        }
        unsigned m0 = __ballot_sync(0xffffffffu, t0 == clsv);
        unsigned m1 = __ballot_sync(0xffffffffu, t1 == clsv);
        unsigned m2 = __ballot_sync(0xffffffffu, t2 == clsv);
        if (wc == 0) cnt += __popc(m0) + __popc(m1) + __popc(m2);
        // polarity identity: own bit set  -> dp = dist to nearest zero, dn = 0
        //                    own bit clear-> dp = 0, dn = dist to nearest set
        unsigned mw = (wc == 0) ? m0 : (wc == 1) ? m1 : m2;
        unsigned x = (unsigned)(-(int)((mw >> lane) & 1u));   // bit ? ~0 : 0
        int d = near_zero_dist(m0 ^ x, m1 ^ x, m2 ^ x, wc, lane);
        int dsq = (d > 95) ? SENTI : d * d;
        int h2 = h * h;
        int fp = (x ? dsq : 0) + h2;
        int fn = (x ? 0 : dsq) + h2;
        sh[lane * 97 + h] = make_float2((float)min(fp, SENTI),
                                        (float)min(fn, SENTI));
    }
    if (wc == 0 && lane == 0) atomicAdd(&scnt, cnt);
    __syncthreads();
    if (wc == 0 && threadIdx.x == 0) g_cntpart[vb * 96 + s] = (unsigned)scnt;
    if (bid == 0 && threadIdx.x == 0) g_sum = 0ULL;

    // phase 2: min-conv along h for this thread's 6 outputs at w-row tx
    int tx = lane, ty = wid;
    int i0 = ty * 6;
    const float2* sp = sh + tx * 97;

    float fi[6];
    #pragma unroll
    for (int k = 0; k < 6; k++) fi[k] = (float)(i0 + k);

    // per-warp exact window: R >= sqrt(f[i]) for every output in the warp
    float fm = 0.f;
    #pragma unroll
    for (int k = 0; k < 6; k++) {
        float2 u = sp[i0 + k];
        fm = fmaxf(fm, fmaxf(u.x, u.y) - fi[k] * fi[k]);
    }
    #pragma unroll
    for (int off = 16; off; off >>= 1)
        fm = fmaxf(fm, __shfl_xor_sync(0xffffffffu, fm, off));
    int R = (fm >= THRSF) ? 95 : min(95, (int)floorf(fsqrt_pos(fm)) + 1);

    int j0 = max(0, i0 - R), j1 = min(95, i0 + 5 + R);
    float v0[6], v1[6];
    #pragma unroll
    for (int k = 0; k < 6; k++) { v0[k] = 3.0e38f; v1[k] = 3.0e38f; }

    float m2a = -2.0f * (float)j0;
    int j = j0;
    for (; j + 1 <= j1; j += 2) {
        float2 a = sp[j], bb = sp[j + 1];
        float m2b = m2a - 2.0f;
        #pragma unroll
        for (int k = 0; k < 6; k++) {
            v0[k] = fminf(v0[k], fmaf(m2a, fi[k], a.x));
            v1[k] = fminf(v1[k], fmaf(m2a, fi[k], a.y));
            v0[k] = fminf(v0[k], fmaf(m2b, fi[k], bb.x));
            v1[k] = fminf(v1[k], fmaf(m2b, fi[k], bb.y));
        }
        m2a -= 4.0f;
    }
    if (j == j1) {
        float2 a = sp[j];
        #pragma unroll
        for (int k = 0; k < 6; k++) {
            v0[k] = fminf(v0[k], fmaf(m2a, fi[k], a.x));
            v1[k] = fminf(v1[k], fmaf(m2a, fi[k], a.y));
        }
    }

    unsigned* outp = g_pack + (size_t)vb * N3 + (size_t)s * N2 + wc * 32 + tx;
    #pragma unroll
    for (int k = 0; k < 6; k++) {
        float i2 = fi[k] * fi[k];
        float r0 = v0[k] + i2;
        float r1 = v1[k] + i2;
        unsigned e0 = (r0 >= THRSF) ? (unsigned)SENTI : (unsigned)__float2int_rn(r0);
        unsigned e1 = (r1 >= THRSF) ? (unsigned)SENTI : (unsigned)__float2int_rn(r1);
        outp[(size_t)(i0 + k) * 96] = e0 | (e1 << 16);
    }
}

// ------------------------------------------- fused D pass + softmax reduce
// Grid: 4 packed vols (b,cls) * 96 h-slices * 3 w-chunks = 1152 blocks x 512.
__global__ void __launch_bounds__(512, 4) k_fuse_d(const float* __restrict__ logits,
                                                   float* __restrict__ outp) {
    __shared__ float2 sh[96 * 32];     // 24.6 KB: [d-row][w]
    __shared__ float swred[16];
    int bid = blockIdx.x;
    int vb = bid / 288, rem = bid % 288;
    int s = rem / 3, wc = rem % 3;
    int b = vb >> 1, cls = vb & 1;
    int tx = threadIdx.x & 31, ty = threadIdx.x >> 5;
    unsigned nbase = (unsigned)s * 96 + wc * 32 + tx;   // voxel idx: + d*N2

    // gate = mask.any() for this (b, cls): OR over its 96 per-slice counts
    int pred = (threadIdx.x < 96) ? (g_cntpart[vb * 96 + threadIdx.x] != 0) : 0;
    float gate = __syncthreads_or(pred) ? 1.f : 0.f;

    const unsigned* p = g_pack + (size_t)vb * N3 + nbase;
    #pragma unroll
    for (int r = ty; r < 96; r += 16) {
        unsigned u = p[(size_t)r * N2];
        float r2 = (float)(r * r);
        sh[r * 32 + tx] = make_float2((float)(u & 0xffffu) + r2,
                                      (float)(u >> 16) + r2);
    }
    __syncthreads();

    int i0 = ty * 6;
    float fi[6];
    #pragma unroll
    for (int k = 0; k < 6; k++) fi[k] = (float)(i0 + k);

    const float2* sp = sh + tx;

    // per-warp exact window radius
    float fm = 0.f;
    #pragma unroll
    for (int k = 0; k < 6; k++) {
        float2 u = sp[(i0 + k) * 32];
        fm = fmaxf(fm, fmaxf(u.x, u.y) - fi[k] * fi[k]);
    }
    #pragma unroll
    for (int off = 16; off; off >>= 1)
        fm = fmaxf(fm, __shfl_xor_sync(0xffffffffu, fm, off));
    int R = (fm >= THRSF) ? 95 : min(95, (int)floorf(fsqrt_pos(fm)) + 1);

    int j0 = max(0, i0 - R), j1 = min(95, i0 + 5 + R);
    float v0[6], v1[6];
    #pragma unroll
    for (int k = 0; k < 6; k++) { v0[k] = 3.0e38f; v1[k] = 3.0e38f; }

    float m2a = -2.0f * (float)j0;
    int j = j0;
    for (; j + 1 <= j1; j += 2) {
        float2 a = sp[j * 32], bb = sp[j * 32 + 32];
        float m2b = m2a - 2.0f;
        #pragma unroll
        for (int k = 0; k < 6; k++) {
            v0[k] = fminf(v0[k], fmaf(m2a, fi[k], a.x));
            v1[k] = fminf(v1[k], fmaf(m2a, fi[k], a.y));
            v0[k] = fminf(v0[k], fmaf(m2b, fi[k], bb.x));
            v1[k] = fminf(v1[k], fmaf(m2b, fi[k], bb.y));
        }
        m2a -= 4.0f;
    }
    if (j == j1) {
        float2 a = sp[j * 32];
        #pragma unroll
        for (int k = 0; k < 6; k++) {
            v0[k] = fminf(v0[k], fmaf(m2a, fi[k], a.x));
            v1[k] = fminf(v1[k], fmaf(m2a, fi[k], a.y));
        }
    }

    // epilogue: sd = sqrt(neg) - sqrt(pos); 2-exp softmax of this class; gate
    const float* L = logits + (size_t)b * 3 * N3 + nbase + (size_t)i0 * N2;
    float acc = 0.f;
    #pragma unroll
    for (int k = 0; k < 6; k++) {
        float i2 = fi[k] * fi[k];
        float r0 = v0[k] + i2;
        float r1 = v1[k] + i2;
        float f0 = (r0 >= THRSF) ? 1e8f : r0;
        float f1 = (r1 >= THRSF) ? 1e8f : r1;
        float sd = fsqrt_pos(f1) - fsqrt_pos(f0);
        float l0 = L[0], l1 = L[(size_t)N3], l2 = L[(size_t)2 * N3];
        L += N2;
        // p_c = 1 / (e^{l0-lc} + e^{lo-lc} + 1), own term == 1
        float lc = cls ? l2 : l1;
        float lo = cls ? l1 : l2;
        float sum = __expf(l0 - lc) + __expf(lo - lc) + 1.0f;
        acc += __fdividef(sd, sum);
    }
    acc *= gate;

    #pragma unroll
    for (int off = 16; off; off >>= 1)
        acc += __shfl_down_sync(0xffffffffu, acc, off);
    if (tx == 0) swred[ty] = acc;
    __syncthreads();
    if (threadIdx.x == 0) {
        float t = 0.f;
        #pragma unroll
        for (int i = 0; i < 16; i++) t += swred[i];
        // exact power-of-two scale -> deterministic integer accumulation
        long long q = llrintf(t * 16777216.0f);
        atomicAdd(&g_sum, (unsigned long long)q);
        __threadfence();
        unsigned tk = atomicAdd(&g_tick, 1u);
        if ((tk % 1152u) == 1151u) {
            long long ssum = (long long)atomicAdd(&g_sum, 0ULL);
            outp[0] = (float)((double)ssum / 16777216.0 / (2.0 * (double)N3));
        }
    }
}

// ---------------------------------------------------------------- launch
extern "C" void kernel_launch(void* const* d_in, const int* in_sizes, int n_in,
                              void* d_out, int out_size) {
    const float* logits = (const float*)d_in[0];
    const void*  targets = d_in[1];
    float* out = (float*)d_out;
    (void)in_sizes; (void)n_in; (void)out_size;

    k_wh<<<1152, 512>>>(targets);
    k_fuse_d<<<1152, 512>>>(logits, out);
}

// round 16
// speedup vs baseline: 1.1915x; 1.0907x over previous
#include <cuda_runtime.h>
#include <math.h>

// BoundaryLoss: exact squared-EDT via separable min-convolution. 2 kernels.
// Hot min-conv loops: packed f32x2 candidate generation (fma2/add2, one pair
// of fields per instruction) + scalar FMNMX mins on the free register halves.
// k_wh:     ballot targets -> nearest-opposite-bit W distance -> windowed H
//           min-conv -> packed u32 store.
// k_fuse_d: windowed D min-conv + 2-exp softmax + rsqrt signed-dist +
//           deterministic fixed-point reduction.
// Shapes: B=2, C=3, D=H=W=96.

#define N2 9216           // 96*96
#define N3 884736         // 96^3
#define SENTI 65535
#define THRSF 32768.0f    // real <= 27075 < 32768 <= sentinel-derived

__device__ unsigned g_pack[4 * N3];    // 14.2 MB packed scratch (pos|neg<<16)
__device__ unsigned g_cntpart[384];    // per (vol, d-slice) mask counts
__device__ unsigned long long g_sum;   // fixed-point (x 2^24) loss numerator
__device__ unsigned g_tick = 0;        // monotonic ticket (mod 1152 per launch)

// fast exact-enough sqrt: one MUFU.RSQ + one FMUL; x=0 -> 0 (not NaN)
__device__ __forceinline__ float fsqrt_pos(float x) {
    return x * rsqrtf(x + 1e-20f);
}

// ---------------- packed f32x2 helpers (sm_100a; min.f32x2 does NOT exist)
typedef unsigned long long u64;
__device__ __forceinline__ u64 pk2(float x, float y) {
    u64 r; asm("mov.b64 %0, {%1, %2};" : "=l"(r) : "f"(x), "f"(y)); return r;
}
__device__ __forceinline__ void upk2(u64 v, float& x, float& y) {
    asm("mov.b64 {%0, %1}, %2;" : "=f"(x), "=f"(y) : "l"(v));   // reg-pair: free
}
__device__ __forceinline__ u64 fma2_(u64 a, u64 b, u64 c) {
    u64 d; asm("fma.rn.f32x2 %0, %1, %2, %3;" : "=l"(d) : "l"(a), "l"(b), "l"(c)); return d;
}
__device__ __forceinline__ u64 add2_(u64 a, u64 b) {
    u64 d; asm("add.rn.f32x2 %0, %1, %2;" : "=l"(d) : "l"(a), "l"(b)); return d;
}

// Packed-candidate windowed min-conv for 6 outputs (both fields).
// Candidate pair for output k at j: c_k = (f+j^2) - 2j*(i0+k); c_{k+1}=c_k-2j.
// All quantities exact integers in fp32 -> bit-exact.
template<int STRIDE>
__device__ __forceinline__ void minconv6p(const u64* __restrict__ spu,
                                          int j0, int j1, float fi0,
                                          float v0[6], float v1[6]) {
    float m2a = -2.0f * (float)j0;
    u64 fi02 = pk2(fi0, fi0);
    u64 m2a2 = pk2(m2a, m2a);
    const u64 cm2 = pk2(-2.f, -2.f);
    const u64 cm4 = pk2(-4.f, -4.f);
    int j = j0;
    for (; j + 1 <= j1; j += 2) {
        u64 a = spu[(size_t)j * STRIDE];
        u64 b = spu[(size_t)(j + 1) * STRIDE];
        u64 m2b2 = add2_(m2a2, cm2);
        u64 ca = fma2_(m2a2, fi02, a);
        u64 cb = fma2_(m2b2, fi02, b);
        #pragma unroll
        for (int k = 0; k < 6; k++) {
            float cax, cay, cbx, cby;
            upk2(ca, cax, cay); upk2(cb, cbx, cby);
            v0[k] = fminf(v0[k], cax); v1[k] = fminf(v1[k], cay);
            v0[k] = fminf(v0[k], cbx); v1[k] = fminf(v1[k], cby);
            if (k < 5) { ca = add2_(ca, m2a2); cb = add2_(cb, m2b2); }
        }
        m2a2 = add2_(m2a2, cm4);
    }
    if (j == j1) {
        u64 a = spu[(size_t)j * STRIDE];
        u64 ca = fma2_(m2a2, fi02, a);
        #pragma unroll
        for (int k = 0; k < 6; k++) {
            float cax, cay;
            upk2(ca, cax, cay);
            v0[k] = fminf(v0[k], cax); v1[k] = fminf(v1[k], cay);
            if (k < 5) ca = add2_(ca, m2a2);
        }
    }
}

// ------------------------------------- nearest SET bit in 96-bit mask
__device__ __forceinline__ int near_zero_dist(unsigned z0, unsigned z1, unsigned z2,
                                              int w, int r) {
    unsigned lowm = (2u << r) - 1u;
    unsigned him  = 0xffffffffu << r;
    int dl = 1000, dr = 1000;
    if (w == 0) {
        unsigned u = z0 & lowm;
        if (u) dl = r - (31 - __clz(u));
        unsigned v = z0 & him;
        if (v)       dr = (__ffs(v) - 1) - r;
        else if (z1) dr = 32 - r + (__ffs(z1) - 1);
        else if (z2) dr = 64 - r + (__ffs(z2) - 1);
    } else if (w == 1) {
        unsigned u = z1 & lowm;
        if (u)       dl = r - (31 - __clz(u));
        else if (z0) dl = r + 1 + __clz(z0);
        unsigned v = z1 & him;
        if (v)       dr = (__ffs(v) - 1) - r;
        else if (z2) dr = 32 - r + (__ffs(z2) - 1);
    } else {
        unsigned u = z2 & lowm;
        if (u)       dl = r - (31 - __clz(u));
        else if (z1) dl = r + 1 + __clz(z1);
        else if (z0) dl = r + 33 + __clz(z0);
        unsigned v = z2 & him;
        if (v) dr = (__ffs(v) - 1) - r;
    }
    return min(dl, dr);
}

// --------------------------------------------------- fused W + H pass
// Grid: 1152 = vb(2b x 2cls)*288 + d-slice*3 + w-chunk ; 512 threads.
__global__ void __launch_bounds__(512, 3) k_wh(const void* __restrict__ tptr) {
    __shared__ float2 sh[32 * 97];     // [w-row][h], pitch 97
    __shared__ int scnt;
    int bid = blockIdx.x;
    int vb = bid / 288, rem = bid % 288;
    int s = rem / 3, wc = rem % 3;
    int b = vb >> 1, clsv = (vb & 1) + 1;
    int lane = threadIdx.x & 31, wid = threadIdx.x >> 5;   // 16 warps

    const int* t32 = (const int*)tptr;
    if (threadIdx.x == 0) scnt = 0;
    // dtype probe: int64 targets in [0,2] -> all odd int32 words zero
    int any = (threadIdx.x < 64) ? (t32[2 * threadIdx.x + 1] != 0) : 0;
    int is64 = !__syncthreads_or(any);   // also orders scnt init

    int tb = b * N3 + s * N2;
    int cnt = 0;
    #pragma unroll
    for (int k = 0; k < 6; k++) {
        int h = wid + 16 * k;
        int t0, t1, t2;
        if (!is64) {
            const int* T = t32 + tb + h * 96;
            t0 = T[lane]; t1 = T[lane + 32]; t2 = T[lane + 64];
        } else {
            const long long* T = (const long long*)tptr + tb + h * 96;
            t0 = (int)T[lane]; t1 = (int)T[lane + 32]; t2 = (int)T[lane + 64];
        }
        unsigned m0 = __ballot_sync(0xffffffffu, t0 == clsv);
        unsigned m1 = __ballot_sync(0xffffffffu, t1 == clsv);
        unsigned m2 = __ballot_sync(0xffffffffu, t2 == clsv);
        if (wc == 0) cnt += __popc(m0) + __popc(m1) + __popc(m2);
        // polarity identity: own bit set  -> dp = dist to nearest zero, dn = 0
        unsigned mw = (wc == 0) ? m0 : (wc == 1) ? m1 : m2;
        unsigned x = (unsigned)(-(int)((mw >> lane) & 1u));   // bit ? ~0 : 0
        int d = near_zero_dist(m0 ^ x, m1 ^ x, m2 ^ x, wc, lane);
        int dsq = (d > 95) ? SENTI : d * d;
        int h2 = h * h;
        int fp = (x ? dsq : 0) + h2;
        int fn = (x ? 0 : dsq) + h2;
        sh[lane * 97 + h] = make_float2((float)min(fp, SENTI),
                                        (float)min(fn, SENTI));
    }
    if (wc == 0 && lane == 0) atomicAdd(&scnt, cnt);
    __syncthreads();
    if (wc == 0 && threadIdx.x == 0) g_cntpart[vb * 96 + s] = (unsigned)scnt;
    if (bid == 0 && threadIdx.x == 0) g_sum = 0ULL;

    // phase 2: min-conv along h for this thread's 6 outputs at w-row tx
    int tx = lane, ty = wid;
    int i0 = ty * 6;
    const float2* sp = sh + tx * 97;

    // per-warp exact window: R >= sqrt(f[i]) for every output in the warp
    float fm = 0.f;
    #pragma unroll
    for (int k = 0; k < 6; k++) {
        float2 u = sp[i0 + k];
        float fik = (float)(i0 + k);
        fm = fmaxf(fm, fmaxf(u.x, u.y) - fik * fik);
    }
    #pragma unroll
    for (int off = 16; off; off >>= 1)
        fm = fmaxf(fm, __shfl_xor_sync(0xffffffffu, fm, off));
    int R = (fm >= THRSF) ? 95 : min(95, (int)floorf(fsqrt_pos(fm)) + 1);

    int j0 = max(0, i0 - R), j1 = min(95, i0 + 5 + R);
    float v0[6], v1[6];
    #pragma unroll
    for (int k = 0; k < 6; k++) { v0[k] = 3.0e38f; v1[k] = 3.0e38f; }
    minconv6p<1>((const u64*)sp, j0, j1, (float)i0, v0, v1);

    unsigned* outp = g_pack + (size_t)vb * N3 + (size_t)s * N2 + wc * 32 + tx;
    #pragma unroll
    for (int k = 0; k < 6; k++) {
        float i2 = (float)((i0 + k) * (i0 + k));
        float r0 = v0[k] + i2;
        float r1 = v1[k] + i2;
        unsigned e0 = (r0 >= THRSF) ? (unsigned)SENTI : (unsigned)__float2int_rn(r0);
        unsigned e1 = (r1 >= THRSF) ? (unsigned)SENTI : (unsigned)__float2int_rn(r1);
        outp[(size_t)(i0 + k) * 96] = e0 | (e1 << 16);
    }
}

// ------------------------------------------- fused D pass + softmax reduce
// Grid: 4 packed vols (b,cls) * 96 h-slices * 3 w-chunks = 1152 blocks x 512.
__global__ void __launch_bounds__(512, 4) k_fuse_d(const float* __restrict__ logits,
                                                   float* __restrict__ outp) {
    __shared__ float2 sh[96 * 32];     // 24.6 KB: [d-row][w]
    __shared__ float swred[16];
    int bid = blockIdx.x;
    int vb = bid / 288, rem = bid % 288;
    int s = rem / 3, wc = rem % 3;
    int b = vb >> 1, cls = vb & 1;
    int tx = threadIdx.x & 31, ty = threadIdx.x >> 5;
    unsigned nbase = (unsigned)s * 96 + wc * 32 + tx;   // voxel idx: + d*N2

    // gate = mask.any() for this (b, cls): OR over its 96 per-slice counts
    int pred = (threadIdx.x < 96) ? (g_cntpart[vb * 96 + threadIdx.x] != 0) : 0;
    float gate = __syncthreads_or(pred) ? 1.f : 0.f;

    const unsigned* p = g_pack + (size_t)vb * N3 + nbase;
    #pragma unroll
    for (int r = ty; r < 96; r += 16) {
        unsigned u = p[(size_t)r * N2];
        float r2 = (float)(r * r);
        sh[r * 32 + tx] = make_float2((float)(u & 0xffffu) + r2,
                                      (float)(u >> 16) + r2);
    }
    __syncthreads();

    int i0 = ty * 6;
    const float2* sp = sh + tx;

    // per-warp exact window radius
    float fm = 0.f;
    #pragma unroll
    for (int k = 0; k < 6; k++) {
        float2 u = sp[(i0 + k) * 32];
        float fik = (float)(i0 + k);
        fm = fmaxf(fm, fmaxf(u.x, u.y) - fik * fik);
    }
    #pragma unroll
    for (int off = 16; off; off >>= 1)
        fm = fmaxf(fm, __shfl_xor_sync(0xffffffffu, fm, off));
    int R = (fm >= THRSF) ? 95 : min(95, (int)floorf(fsqrt_pos(fm)) + 1);

    int j0 = max(0, i0 - R), j1 = min(95, i0 + 5 + R);
    float v0[6], v1[6];
    #pragma unroll
    for (int k = 0; k < 6; k++) { v0[k] = 3.0e38f; v1[k] = 3.0e38f; }
    minconv6p<32>((const u64*)sp, j0, j1, (float)i0, v0, v1);

    // epilogue: sd = sqrt(neg) - sqrt(pos); 2-exp softmax of this class; gate
    const float* L = logits + (size_t)b * 3 * N3 + nbase + (size_t)i0 * N2;
    float acc = 0.f;
    #pragma unroll
    for (int k = 0; k < 6; k++) {
        float i2 = (float)((i0 + k) * (i0 + k));
        float r0 = v0[k] + i2;
        float r1 = v1[k] + i2;
        float f0 = (r0 >= THRSF) ? 1e8f : r0;
        float f1 = (r1 >= THRSF) ? 1e8f : r1;
        float sd = fsqrt_pos(f1) - fsqrt_pos(f0);
        float l0 = L[0], l1 = L[(size_t)N3], l2 = L[(size_t)2 * N3];
        L += N2;
        // p_c = 1 / (e^{l0-lc} + e^{lo-lc} + 1), own term == 1
        float lc = cls ? l2 : l1;
        float lo = cls ? l1 : l2;
        float sum = __expf(l0 - lc) + __expf(lo - lc) + 1.0f;
        acc += __fdividef(sd, sum);
    }
    acc *= gate;

    #pragma unroll
    for (int off = 16; off; off >>= 1)
        acc += __shfl_down_sync(0xffffffffu, acc, off);
    if (tx == 0) swred[ty] = acc;
    __syncthreads();
    if (threadIdx.x == 0) {
        float t = 0.f;
        #pragma unroll
        for (int i = 0; i < 16; i++) t += swred[i];
        // exact power-of-two scale -> deterministic integer accumulation
        long long q = llrintf(t * 16777216.0f);
        atomicAdd(&g_sum, (unsigned long long)q);
        __threadfence();
        unsigned tk = atomicAdd(&g_tick, 1u);
        if ((tk % 1152u) == 1151u) {
            long long ssum = (long long)atomicAdd(&g_sum, 0ULL);
            outp[0] = (float)((double)ssum / 16777216.0 / (2.0 * (double)N3));
        }
    }
}

// ---------------------------------------------------------------- launch
extern "C" void kernel_launch(void* const* d_in, const int* in_sizes, int n_in,
                              void* d_out, int out_size) {
    const float* logits = (const float*)d_in[0];
    const void*  targets = d_in[1];
    float* out = (float*)d_out;
    (void)in_sizes; (void)n_in; (void)out_size;

    k_wh<<<1152, 512>>>(targets);
    k_fuse_d<<<1152, 512>>>(logits, out);
}